// round 3
// baseline (speedup 1.0000x reference)
#include <cuda_runtime.h>
#include <cstdint>

#define N_NODES 50000
#define N_EDGES 800000

typedef unsigned long long ull;

// ---------------- scratch (device globals; no allocation allowed) ----------
__device__ float g_h[N_NODES * 64];        // node features
__device__ float g_NP[N_NODES * 256];      // per-node projections f_t|f_s|s_t|s_s
__device__ float g_agg[N_NODES * 64];      // message accumulator
__device__ float g_Wcomb[41 * 384];        // edge_attr -> all-layer gate/core pre-act
__device__ float g_bcomb[384];
__device__ float g_Wnode[3 * 64 * 256];    // per-layer node projection weights
__device__ float g_stats[128];             // BN column sums / sumsq
__device__ int   g_ei32[2 * N_EDGES];      // converted edge indices (src | tgt)
__device__ int   g_is64;                   // detected index dtype

// ---------------- f32x2 helpers --------------------------------------------
__device__ __forceinline__ ull fma2(ull a, ull b, ull c) {
    ull d;
    asm("fma.rn.f32x2 %0, %1, %2, %3;" : "=l"(d) : "l"(a), "l"(b), "l"(c));
    return d;
}
__device__ __forceinline__ ull dup2(float v) {
    ull d; unsigned u = __float_as_uint(v);
    asm("mov.b64 %0, {%1, %2};" : "=l"(d) : "r"(u), "r"(u));
    return d;
}
__device__ __forceinline__ float2 unpack2(ull v) {
    unsigned lo, hi;
    asm("mov.b64 {%0, %1}, %2;" : "=r"(lo), "=r"(hi) : "l"(v));
    return make_float2(__uint_as_float(lo), __uint_as_float(hi));
}
__device__ __forceinline__ void red2(float* p, float a, float b) {
    asm volatile("red.global.add.v2.f32 [%0], {%1, %2};" :: "l"(p), "f"(a), "f"(b) : "memory");
}
__device__ __forceinline__ float sigmoidf_(float x) {
    return __fdividef(1.f, 1.f + __expf(-x));
}
__device__ __forceinline__ float softplusf_(float x) {
    return fmaxf(x, 0.f) + __logf(1.f + __expf(-fabsf(x)));
}

// ---------------- index dtype detection + conversion ------------------------
// int64-encoded small non-negative indices: every odd int32 word is zero.
__global__ void detect_kernel(const int* __restrict__ raw32) {
    if (threadIdx.x == 0) {
        int is64 = 1;
        for (int i = 0; i < 64; i++) {
            if (raw32[2 * i + 1] != 0) { is64 = 0; break; }
        }
        g_is64 = is64;
    }
}

__global__ void convert_kernel(const void* __restrict__ raw) {
    const int i = blockIdx.x * blockDim.x + threadIdx.x;
    if (i >= 2 * N_EDGES) return;
    int v;
    if (g_is64) v = (int)((const long long*)raw)[i];
    else        v = ((const int*)raw)[i];
    v = min(max(v, 0), N_NODES - 1);   // safety clamp: wrong answer > crash
    g_ei32[i] = v;
}

// ---------------- weight pre-combination (one small block) -----------------
__global__ void combine_kernel(const float* __restrict__ Wf, const float* __restrict__ bf,
                               const float* __restrict__ Ws, const float* __restrict__ bs,
                               const float* __restrict__ W2, const float* __restrict__ b2) {
    const int c = threadIdx.x;                 // 0..383
    const int i = c >> 7;                      // layer
    const int r = c & 127;
    const bool isF = r < 64;
    const int j = r & 63;
    const float* WB = isF ? Wf : Ws;
    const float* bB = isF ? bf : bs;

    float wc[64];
#pragma unroll
    for (int k = 0; k < 64; k++) wc[k] = WB[i * 12288 + (128 + k) * 64 + j];

    float bacc = bB[i * 64 + j];
#pragma unroll
    for (int k = 0; k < 64; k++) bacc += b2[k] * wc[k];
    g_bcomb[c] = bacc;

    for (int a = 0; a < 41; a++) {
        float acc = 0.f;
#pragma unroll
        for (int k = 0; k < 64; k++) acc += W2[a * 64 + k] * wc[k];
        g_Wcomb[a * 384 + c] = acc;
    }

    // node-projection weight assembly: [l][k][part*64+jj]
    for (int idx = c; idx < 3 * 64 * 256; idx += 384) {
        int l = idx >> 14;
        int rem = idx & 16383;
        int k = rem >> 8;
        int cc = rem & 255;
        int part = cc >> 6;                    // 0:f_t 1:f_s 2:s_t 3:s_s
        int jj = cc & 63;
        const float* S = (part < 2) ? Wf : Ws;
        int row = k + ((part & 1) ? 64 : 0);
        g_Wnode[idx] = S[l * 12288 + row * 64 + jj];
    }
}

// ---------------- 16-row f32x2 GEMM: out = A[M,K] @ W[K,2*CP*NT] (+bias) ---
template <int K, int NT, int CP>
__global__ void __launch_bounds__(NT) gemm16(const float* __restrict__ A,
                                             const float* __restrict__ W, int ldw,
                                             const float* __restrict__ bias,
                                             float* __restrict__ out, int ldo) {
    __shared__ __align__(16) ull a_s[16][(K + 1) & ~1];
    const int tid = threadIdx.x;
    const int row0 = blockIdx.x * 16;

    for (int idx = tid; idx < 16 * K; idx += NT) {
        int r = idx / K, k = idx - r * K;
        a_s[r][k] = dup2(A[(size_t)row0 * K + idx]);
    }
    if (K & 1) {
        for (int r = tid; r < 16; r += NT) a_s[r][K] = 0ull;
    }
    __syncthreads();

    const int c = tid * 2 * CP;
    ull acc[16][CP];
#pragma unroll
    for (int r = 0; r < 16; r++)
#pragma unroll
        for (int p = 0; p < CP; p++) acc[r][p] = 0ull;

    const float* Wc = W + c;
#pragma unroll 2
    for (int kk = 0; kk < (K + 1) / 2; kk++) {
        const int k0 = 2 * kk;
        ull w0[CP], w1[CP];
        if (CP == 2) {
            // device-global weights, 16B aligned
            ulonglong2 wv = *(const ulonglong2*)(Wc + (size_t)k0 * ldw);
            w0[0] = wv.x; w0[CP - 1] = wv.y;
        } else {
            w0[0] = *(const ull*)(Wc + (size_t)k0 * ldw);
        }
        if (k0 + 1 < K) {
            if (CP == 2) {
                ulonglong2 wv = *(const ulonglong2*)(Wc + (size_t)(k0 + 1) * ldw);
                w1[0] = wv.x; w1[CP - 1] = wv.y;
            } else {
                w1[0] = *(const ull*)(Wc + (size_t)(k0 + 1) * ldw);
            }
        } else {
#pragma unroll
            for (int p = 0; p < CP; p++) w1[p] = 0ull;
        }
#pragma unroll
        for (int r = 0; r < 16; r++) {
            ulonglong2 av = *(const ulonglong2*)&a_s[r][k0];
#pragma unroll
            for (int p = 0; p < CP; p++) {
                acc[r][p] = fma2(w0[p], av.x, acc[r][p]);
                acc[r][p] = fma2(w1[p], av.y, acc[r][p]);
            }
        }
    }

    float2 b[CP];
#pragma unroll
    for (int p = 0; p < CP; p++) {
        b[p] = make_float2(0.f, 0.f);
        if (bias) b[p] = *(const float2*)(bias + c + 2 * p);
    }
#pragma unroll
    for (int r = 0; r < 16; r++) {
#pragma unroll
        for (int p = 0; p < CP; p++) {
            float2 v = unpack2(acc[r][p]);
            v.x += b[p].x; v.y += b[p].y;
            *(float2*)&out[(size_t)(row0 + r) * ldo + c + 2 * p] = v;
        }
    }
}

// ---------------- fused edge kernel: GEMM + gather + act + scatter ---------
__global__ void __launch_bounds__(32) edge_kernel(const float* __restrict__ ea,
                                                  int layer) {
    __shared__ __align__(16) ull ea_s[16][42];
    __shared__ int src_s[16], tgt_s[16];
    const int tid = threadIdx.x;
    const int e0 = blockIdx.x * 16;

    if (tid < 16) src_s[tid] = g_ei32[e0 + tid];
    else          tgt_s[tid - 16] = g_ei32[N_EDGES + e0 + (tid - 16)];

    for (int idx = tid; idx < 16 * 41; idx += 32) {
        int r = idx / 41, k = idx - r * 41;
        ea_s[r][k] = dup2(ea[(size_t)e0 * 41 + idx]);
    }
    if (tid < 16) ea_s[tid][41] = 0ull;
    __syncwarp();

    const float* Wl = g_Wcomb + layer * 128 + 2 * tid;  // gate cols; core at +64
    ull accG[16], accC[16];
#pragma unroll
    for (int r = 0; r < 16; r++) { accG[r] = 0ull; accC[r] = 0ull; }

#pragma unroll 3
    for (int kk = 0; kk < 21; kk++) {
        const int k0 = 2 * kk;
        ull wg0 = *(const ull*)(Wl + k0 * 384);
        ull wc0 = *(const ull*)(Wl + k0 * 384 + 64);
        ull wg1 = 0ull, wc1 = 0ull;
        if (k0 + 1 < 41) {
            wg1 = *(const ull*)(Wl + (k0 + 1) * 384);
            wc1 = *(const ull*)(Wl + (k0 + 1) * 384 + 64);
        }
#pragma unroll
        for (int r = 0; r < 16; r++) {
            ulonglong2 av = *(const ulonglong2*)&ea_s[r][k0];
            accG[r] = fma2(wg0, av.x, accG[r]);
            accG[r] = fma2(wg1, av.y, accG[r]);
            accC[r] = fma2(wc0, av.x, accC[r]);
            accC[r] = fma2(wc1, av.y, accC[r]);
        }
    }

    const int cg = 2 * tid;
    const float2 bg = *(const float2*)(g_bcomb + layer * 128 + cg);
    const float2 bc = *(const float2*)(g_bcomb + layer * 128 + 64 + cg);

#pragma unroll
    for (int r = 0; r < 16; r++) {
        const int tn = tgt_s[r], sn = src_s[r];
        const float* NPt = g_NP + (size_t)tn * 256;
        const float* NPs = g_NP + (size_t)sn * 256;
        float2 g = unpack2(accG[r]);
        float2 cp = unpack2(accC[r]);
        float2 a1 = *(const float2*)(NPt + cg);          // f_t
        float2 a2 = *(const float2*)(NPs + 64 + cg);     // f_s
        float2 a3 = *(const float2*)(NPt + 128 + cg);    // s_t
        float2 a4 = *(const float2*)(NPs + 192 + cg);    // s_s
        g.x += bg.x + a1.x + a2.x;   g.y += bg.y + a1.y + a2.y;
        cp.x += bc.x + a3.x + a4.x;  cp.y += bc.y + a3.y + a4.y;
        float mx = sigmoidf_(g.x) * softplusf_(cp.x);
        float my = sigmoidf_(g.y) * softplusf_(cp.y);
        red2(g_agg + (size_t)tn * 64 + cg, mx, my);
    }
}

// ---------------- zero agg + stats ------------------------------------------
__global__ void zero_agg_stats() {
    const float4 z = make_float4(0.f, 0.f, 0.f, 0.f);
    const int n4 = N_NODES * 16;
    const int gtid = blockIdx.x * blockDim.x + threadIdx.x;
    for (int i = gtid; i < n4; i += gridDim.x * blockDim.x)
        ((float4*)g_agg)[i] = z;
    if (gtid < 128) g_stats[gtid] = 0.f;
}

// ---------------- residual + BN statistics ---------------------------------
__global__ void __launch_bounds__(256) resid_stats() {
    const int col = threadIdx.x & 63;
    const int rgrp = threadIdx.x >> 6;  // 0..3
    float s = 0.f, q = 0.f;
    for (int row = blockIdx.x * 4 + rgrp; row < N_NODES; row += gridDim.x * 4) {
        const int idx = row * 64 + col;
        float t = g_h[idx] + g_agg[idx];
        g_h[idx] = t;
        s += t; q += t * t;
    }
    atomicAdd(&g_stats[col], s);
    atomicAdd(&g_stats[64 + col], q);
}

// ---------------- BN normalize (+optional relu) -----------------------------
__global__ void __launch_bounds__(256) bn_kernel(const float* __restrict__ gamma,
                                                 const float* __restrict__ beta,
                                                 int layer, float* __restrict__ dst,
                                                 int do_relu) {
    const int i = blockIdx.x * blockDim.x + threadIdx.x;  // exact grid: 3.2M
    const int col = i & 63;
    const float invN = 1.f / (float)N_NODES;
    float mean = g_stats[col] * invN;
    float var = g_stats[64 + col] * invN - mean * mean;
    float inv = rsqrtf(var + 1e-5f);
    float v = (g_h[i] - mean) * inv * gamma[layer * 64 + col] + beta[layer * 64 + col];
    if (do_relu) v = fmaxf(v, 0.f);
    dst[i] = v;
}

// ---------------- launch ----------------------------------------------------
extern "C" void kernel_launch(void* const* d_in, const int* in_sizes, int n_in,
                              void* d_out, int out_size) {
    const float* x   = (const float*)d_in[0];
    const float* ea  = (const float*)d_in[1];
    const void*  ei  = d_in[2];                 // int32 or int64, detected on device
    const float* W1  = (const float*)d_in[3];
    const float* b1  = (const float*)d_in[4];
    const float* W2  = (const float*)d_in[5];
    const float* b2  = (const float*)d_in[6];
    const float* Wf  = (const float*)d_in[7];
    const float* bf  = (const float*)d_in[8];
    const float* Ws  = (const float*)d_in[9];
    const float* bs  = (const float*)d_in[10];
    const float* gamma = (const float*)d_in[11];
    const float* beta  = (const float*)d_in[12];
    float* out = (float*)d_out;

    void *ph, *pnp, *pwn;
    cudaGetSymbolAddress(&ph, g_h);
    cudaGetSymbolAddress(&pnp, g_NP);
    cudaGetSymbolAddress(&pwn, g_Wnode);
    float* hbuf  = (float*)ph;
    float* npbuf = (float*)pnp;
    float* wnode = (float*)pwn;

    detect_kernel<<<1, 32>>>((const int*)ei);
    convert_kernel<<<(2 * N_EDGES + 255) / 256, 256>>>(ei);

    combine_kernel<<<1, 384>>>(Wf, bf, Ws, bs, W2, b2);

    // h0 = x @ W1 + b1   (K=92 -> 64 cols, 2 cols/thread, 32 thr)
    gemm16<92, 32, 1><<<N_NODES / 16, 32>>>(x, W1, 64, b1, hbuf, 64);

    for (int l = 0; l < 3; l++) {
        // NP = h @ Wnode[l]   (K=64 -> 256 cols, 4 cols/thread, 64 thr)
        gemm16<64, 64, 2><<<N_NODES / 16, 64>>>(hbuf, wnode + l * 16384, 256,
                                                (const float*)nullptr, npbuf, 256);
        zero_agg_stats<<<128, 256>>>();
        edge_kernel<<<N_EDGES / 16, 32>>>(ea, l);
        resid_stats<<<256, 256>>>();
        const int last = (l == 2);
        bn_kernel<<<(N_NODES * 64) / 256, 256>>>(gamma, beta, l,
                                                 last ? out : hbuf, last ? 0 : 1);
    }
}

// round 4
// speedup vs baseline: 1.0867x; 1.0867x over previous
#include <cuda_runtime.h>
#include <cstdint>

#define N_NODES 50000
#define N_EDGES 800000

typedef unsigned long long ull;

// ---------------- scratch (device globals; no allocation allowed) ----------
__device__ float g_h[N_NODES * 64];        // node features
__device__ float g_NP[N_NODES * 256];      // per-node projections f_t|f_s|s_t|s_s
__device__ float g_agg[N_NODES * 64];      // message accumulator
__device__ float g_Wcomb[41 * 384];        // edge_attr -> all-layer gate/core pre-act
__device__ ull   g_WcombT[3 * 2 * 32 * 42];// transposed: [layer][mat][lane][k] col-pairs
__device__ float g_bcomb[384];
__device__ float g_Wnode[3 * 64 * 256];    // per-layer node projection weights
__device__ float g_stats[128];             // BN column sums / sumsq
// CSR machinery
__device__ int   g_src32[N_EDGES];
__device__ int   g_tgt32[N_EDGES];
__device__ int   g_deg[N_NODES];
__device__ int   g_cursor[N_NODES];
__device__ int   g_srcperm[N_EDGES];
__device__ int   g_tgtperm[N_EDGES];
__device__ float g_eaperm[(size_t)N_EDGES * 44];  // stride 44, elem 41 zeroed

// ---------------- f32x2 helpers --------------------------------------------
__device__ __forceinline__ ull fma2(ull a, ull b, ull c) {
    ull d;
    asm("fma.rn.f32x2 %0, %1, %2, %3;" : "=l"(d) : "l"(a), "l"(b), "l"(c));
    return d;
}
__device__ __forceinline__ ull dup2(float v) {
    ull d; unsigned u = __float_as_uint(v);
    asm("mov.b64 %0, {%1, %2};" : "=l"(d) : "r"(u), "r"(u));
    return d;
}
__device__ __forceinline__ float2 unpack2(ull v) {
    unsigned lo, hi;
    asm("mov.b64 {%0, %1}, %2;" : "=r"(lo), "=r"(hi) : "l"(v));
    return make_float2(__uint_as_float(lo), __uint_as_float(hi));
}
__device__ __forceinline__ void red2(float* p, float a, float b) {
    asm volatile("red.global.add.v2.f32 [%0], {%1, %2};" :: "l"(p), "f"(a), "f"(b) : "memory");
}
__device__ __forceinline__ float sigmoidf_(float x) {
    return __fdividef(1.f, 1.f + __expf(-x));
}
__device__ __forceinline__ float softplusf_(float x) {
    return fmaxf(x, 0.f) + __logf(1.f + __expf(-fabsf(x)));
}

// ---------------- preprocessing --------------------------------------------
__global__ void zero_deg() {
    const int i = blockIdx.x * blockDim.x + threadIdx.x;
    if (i < N_NODES) g_deg[i] = 0;
}

// detect dtype per block, convert indices, histogram targets
__global__ void __launch_bounds__(256) convert_hist(const void* __restrict__ raw) {
    __shared__ int s_is64;
    if (threadIdx.x == 0) {
        const int* r32 = (const int*)raw;
        int is64 = 1;
        for (int i = 0; i < 64; i++)
            if (r32[2 * i + 1] != 0) { is64 = 0; break; }
        s_is64 = is64;
    }
    __syncthreads();
    const int e = blockIdx.x * 256 + threadIdx.x;
    if (e >= N_EDGES) return;
    int s, t;
    if (s_is64) {
        s = (int)((const long long*)raw)[e];
        t = (int)((const long long*)raw)[N_EDGES + e];
    } else {
        s = ((const int*)raw)[e];
        t = ((const int*)raw)[N_EDGES + e];
    }
    s = min(max(s, 0), N_NODES - 1);
    t = min(max(t, 0), N_NODES - 1);
    g_src32[e] = s;
    g_tgt32[e] = t;
    atomicAdd(&g_deg[t], 1);
}

// single-block exclusive scan of degrees -> g_cursor
__global__ void __launch_bounds__(512) scan_kernel() {
    __shared__ int ssum[512];
    const int t = threadIdx.x;
    const int base = t * 98;
    const int lim = min(base + 98, N_NODES);
    int s = 0;
    for (int i = base; i < lim; i++) s += g_deg[i];
    ssum[t] = s;
    __syncthreads();
    // inclusive Hillis-Steele
    for (int off = 1; off < 512; off <<= 1) {
        int v = (t >= off) ? ssum[t - off] : 0;
        __syncthreads();
        ssum[t] += v;
        __syncthreads();
    }
    int run = ssum[t] - s;  // exclusive prefix for this chunk
    for (int i = base; i < lim; i++) {
        g_cursor[i] = run;
        run += g_deg[i];
    }
}

// scatter into target-sorted order + permute edge_attr rows (stride 44, [41]=0)
__global__ void __launch_bounds__(256) scatter_permute(const float* __restrict__ ea) {
    const int w = threadIdx.x >> 5, lane = threadIdx.x & 31;
    const int eb = blockIdx.x * 256 + w * 32;
    const int e = eb + lane;
    const int tg = g_tgt32[e];
    const int pos = atomicAdd(&g_cursor[tg], 1);
    g_srcperm[pos] = g_src32[e];
    g_tgtperm[pos] = tg;
#pragma unroll 1
    for (int j = 0; j < 32; j++) {
        int pe = __shfl_sync(0xffffffffu, pos, j);
        const float* s = ea + (size_t)(eb + j) * 41;
        float* d = g_eaperm + (size_t)pe * 44;
        d[lane] = s[lane];
        if (lane < 9) d[32 + lane] = s[32 + lane];
        if (lane == 9) d[41] = 0.f;
    }
}

// ---------------- weight pre-combination (one block) ------------------------
__global__ void __launch_bounds__(384) combine_kernel(
    const float* __restrict__ Wf, const float* __restrict__ bf,
    const float* __restrict__ Ws, const float* __restrict__ bs,
    const float* __restrict__ W2, const float* __restrict__ b2) {
    const int c = threadIdx.x;                 // 0..383
    const int i = c >> 7;                      // layer
    const int r = c & 127;
    const bool isF = r < 64;
    const int j = r & 63;
    const float* WB = isF ? Wf : Ws;
    const float* bB = isF ? bf : bs;

    float wc[64];
#pragma unroll
    for (int k = 0; k < 64; k++) wc[k] = WB[i * 12288 + (128 + k) * 64 + j];

    float bacc = bB[i * 64 + j];
#pragma unroll
    for (int k = 0; k < 64; k++) bacc += b2[k] * wc[k];
    g_bcomb[c] = bacc;

    for (int a = 0; a < 41; a++) {
        float acc = 0.f;
#pragma unroll
        for (int k = 0; k < 64; k++) acc += W2[a * 64 + k] * wc[k];
        g_Wcomb[a * 384 + c] = acc;
    }

    // node-projection weight assembly: [l][k][part*64+jj]
    for (int idx = c; idx < 3 * 64 * 256; idx += 384) {
        int l = idx >> 14;
        int rem = idx & 16383;
        int k = rem >> 8;
        int cc = rem & 255;
        int part = cc >> 6;                    // 0:f_t 1:f_s 2:s_t 3:s_s
        int jj = cc & 63;
        const float* S = (part < 2) ? Wf : Ws;
        int row = k + ((part & 1) ? 64 : 0);
        g_Wnode[idx] = S[l * 12288 + row * 64 + jj];
    }

    __syncthreads();

    // transposed col-pair layout: g_WcombT[((layer*2+mat)*32+lane)*42 + k]
    for (int idx = c; idx < 3 * 2 * 32 * 42; idx += 384) {
        int k = idx % 42;
        int rest = idx / 42;
        int lanep = rest & 31;
        rest >>= 5;
        int mat = rest & 1;
        int lay = rest >> 1;
        ull v = 0ull;
        if (k < 41) {
            unsigned lo = __float_as_uint(g_Wcomb[k * 384 + lay * 128 + mat * 64 + 2 * lanep]);
            unsigned hi = __float_as_uint(g_Wcomb[k * 384 + lay * 128 + mat * 64 + 2 * lanep + 1]);
            v = ((ull)hi << 32) | lo;
        }
        g_WcombT[idx] = v;
    }
}

// ---------------- 16-row f32x2 GEMM: out = A[M,K] @ W[K,2*CP*NT] (+bias) ---
template <int K, int NT, int CP>
__global__ void __launch_bounds__(NT) gemm16(const float* __restrict__ A,
                                             const float* __restrict__ W, int ldw,
                                             const float* __restrict__ bias,
                                             float* __restrict__ out, int ldo) {
    __shared__ __align__(16) ull a_s[16][(K + 1) & ~1];
    const int tid = threadIdx.x;
    const int row0 = blockIdx.x * 16;

    for (int idx = tid; idx < 16 * K; idx += NT) {
        int r = idx / K, k = idx - r * K;
        a_s[r][k] = dup2(A[(size_t)row0 * K + idx]);
    }
    if (K & 1) {
        for (int r = tid; r < 16; r += NT) a_s[r][K] = 0ull;
    }
    __syncthreads();

    const int c = tid * 2 * CP;
    ull acc[16][CP];
#pragma unroll
    for (int r = 0; r < 16; r++)
#pragma unroll
        for (int p = 0; p < CP; p++) acc[r][p] = 0ull;

    const float* Wc = W + c;
#pragma unroll 2
    for (int kk = 0; kk < (K + 1) / 2; kk++) {
        const int k0 = 2 * kk;
        ull w0[CP], w1[CP];
        if (CP == 2) {
            ulonglong2 wv = *(const ulonglong2*)(Wc + (size_t)k0 * ldw);
            w0[0] = wv.x; w0[CP - 1] = wv.y;
        } else {
            w0[0] = *(const ull*)(Wc + (size_t)k0 * ldw);
        }
        if (k0 + 1 < K) {
            if (CP == 2) {
                ulonglong2 wv = *(const ulonglong2*)(Wc + (size_t)(k0 + 1) * ldw);
                w1[0] = wv.x; w1[CP - 1] = wv.y;
            } else {
                w1[0] = *(const ull*)(Wc + (size_t)(k0 + 1) * ldw);
            }
        } else {
#pragma unroll
            for (int p = 0; p < CP; p++) w1[p] = 0ull;
        }
#pragma unroll
        for (int r = 0; r < 16; r++) {
            ulonglong2 av = *(const ulonglong2*)&a_s[r][k0];
#pragma unroll
            for (int p = 0; p < CP; p++) {
                acc[r][p] = fma2(w0[p], av.x, acc[r][p]);
                acc[r][p] = fma2(w1[p], av.y, acc[r][p]);
            }
        }
    }

    float2 b[CP];
#pragma unroll
    for (int p = 0; p < CP; p++) {
        b[p] = make_float2(0.f, 0.f);
        if (bias) b[p] = *(const float2*)(bias + c + 2 * p);
    }
#pragma unroll
    for (int r = 0; r < 16; r++) {
#pragma unroll
        for (int p = 0; p < CP; p++) {
            float2 v = unpack2(acc[r][p]);
            v.x += b[p].x; v.y += b[p].y;
            *(float2*)&out[(size_t)(row0 + r) * ldo + c + 2 * p] = v;
        }
    }
}

// ---------------- edge kernel: sorted edges, 8/warp, run-compressed scatter -
__global__ void __launch_bounds__(128) edge_kernel(int layer) {
    __shared__ __align__(16) ull ea_s[4][8][44];
    __shared__ int src_s[4][8], tgt_s[4][8];
    const int w = threadIdx.x >> 5, lane = threadIdx.x & 31;
    const int e0 = (blockIdx.x * 4 + w) * 8;
    const int cg = 2 * lane;

    if (lane < 8)       src_s[w][lane] = g_srcperm[e0 + lane];
    else if (lane < 16) tgt_s[w][lane - 8] = g_tgtperm[e0 + lane - 8];

    // stage 8 edges x 22 float2 = 176 float2 (dup2'd into smem)
#pragma unroll
    for (int j = 0; j < 6; j++) {
        int idx = lane + j * 32;
        if (idx < 176) {
            int r = idx / 22, c2 = idx - r * 22;
            float2 v = *(const float2*)(g_eaperm + (size_t)(e0 + r) * 44 + 2 * c2);
            ulonglong2 pk;
            pk.x = dup2(v.x); pk.y = dup2(v.y);
            *(ulonglong2*)&ea_s[w][r][2 * c2] = pk;
        }
    }
    __syncwarp();

    const ull* WG = g_WcombT + ((size_t)(layer * 2 + 0) * 32 + lane) * 42;
    const ull* WC = g_WcombT + ((size_t)(layer * 2 + 1) * 32 + lane) * 42;

    ull accG[8], accC[8];
#pragma unroll
    for (int r = 0; r < 8; r++) { accG[r] = 0ull; accC[r] = 0ull; }

#pragma unroll
    for (int kk = 0; kk < 21; kk++) {
        ulonglong2 wg = *(const ulonglong2*)(WG + 2 * kk);
        ulonglong2 wc = *(const ulonglong2*)(WC + 2 * kk);
#pragma unroll
        for (int r = 0; r < 8; r++) {
            ulonglong2 av = *(const ulonglong2*)&ea_s[w][r][2 * kk];
            accG[r] = fma2(wg.x, av.x, accG[r]);
            accG[r] = fma2(wg.y, av.y, accG[r]);
            accC[r] = fma2(wc.x, av.x, accC[r]);
            accC[r] = fma2(wc.y, av.y, accC[r]);
        }
    }

    const float2 bg = *(const float2*)(g_bcomb + layer * 128 + cg);
    const float2 bc = *(const float2*)(g_bcomb + layer * 128 + 64 + cg);

    int cur = tgt_s[w][0];
    const float* NPc = g_NP + (size_t)cur * 256;
    float2 ft = *(const float2*)(NPc + cg);
    float2 st = *(const float2*)(NPc + 128 + cg);
    float2 agg = make_float2(0.f, 0.f);

#pragma unroll
    for (int r = 0; r < 8; r++) {
        const int tn = tgt_s[w][r];
        if (tn != cur) {  // warp-uniform branch
            red2(g_agg + (size_t)cur * 64 + cg, agg.x, agg.y);
            cur = tn;
            NPc = g_NP + (size_t)cur * 256;
            ft = *(const float2*)(NPc + cg);
            st = *(const float2*)(NPc + 128 + cg);
            agg.x = 0.f; agg.y = 0.f;
        }
        const float* NPs = g_NP + (size_t)src_s[w][r] * 256;
        float2 fs = *(const float2*)(NPs + 64 + cg);
        float2 ss = *(const float2*)(NPs + 192 + cg);
        float2 g = unpack2(accG[r]);
        float2 cp = unpack2(accC[r]);
        g.x += bg.x + ft.x + fs.x;   g.y += bg.y + ft.y + fs.y;
        cp.x += bc.x + st.x + ss.x;  cp.y += bc.y + st.y + ss.y;
        agg.x += sigmoidf_(g.x) * softplusf_(cp.x);
        agg.y += sigmoidf_(g.y) * softplusf_(cp.y);
    }
    red2(g_agg + (size_t)cur * 64 + cg, agg.x, agg.y);
}

// ---------------- zero agg + stats ------------------------------------------
__global__ void zero_agg_stats() {
    const float4 z = make_float4(0.f, 0.f, 0.f, 0.f);
    const int n4 = N_NODES * 16;
    const int gtid = blockIdx.x * blockDim.x + threadIdx.x;
    for (int i = gtid; i < n4; i += gridDim.x * blockDim.x)
        ((float4*)g_agg)[i] = z;
    if (gtid < 128) g_stats[gtid] = 0.f;
}

// ---------------- residual + BN statistics ---------------------------------
__global__ void __launch_bounds__(256) resid_stats() {
    const int col = threadIdx.x & 63;
    const int rgrp = threadIdx.x >> 6;  // 0..3
    float s = 0.f, q = 0.f;
    for (int row = blockIdx.x * 4 + rgrp; row < N_NODES; row += gridDim.x * 4) {
        const int idx = row * 64 + col;
        float t = g_h[idx] + g_agg[idx];
        g_h[idx] = t;
        s += t; q += t * t;
    }
    atomicAdd(&g_stats[col], s);
    atomicAdd(&g_stats[64 + col], q);
}

// ---------------- BN normalize (+optional relu) -----------------------------
__global__ void __launch_bounds__(256) bn_kernel(const float* __restrict__ gamma,
                                                 const float* __restrict__ beta,
                                                 int layer, float* __restrict__ dst,
                                                 int do_relu) {
    const int i = blockIdx.x * blockDim.x + threadIdx.x;  // exact grid: 3.2M
    const int col = i & 63;
    const float invN = 1.f / (float)N_NODES;
    float mean = g_stats[col] * invN;
    float var = g_stats[64 + col] * invN - mean * mean;
    float inv = rsqrtf(var + 1e-5f);
    float v = (g_h[i] - mean) * inv * gamma[layer * 64 + col] + beta[layer * 64 + col];
    if (do_relu) v = fmaxf(v, 0.f);
    dst[i] = v;
}

// ---------------- launch ----------------------------------------------------
extern "C" void kernel_launch(void* const* d_in, const int* in_sizes, int n_in,
                              void* d_out, int out_size) {
    const float* x   = (const float*)d_in[0];
    const float* ea  = (const float*)d_in[1];
    const void*  ei  = d_in[2];                 // int32 or int64, detected on device
    const float* W1  = (const float*)d_in[3];
    const float* b1  = (const float*)d_in[4];
    const float* W2  = (const float*)d_in[5];
    const float* b2  = (const float*)d_in[6];
    const float* Wf  = (const float*)d_in[7];
    const float* bf  = (const float*)d_in[8];
    const float* Ws  = (const float*)d_in[9];
    const float* bs  = (const float*)d_in[10];
    const float* gamma = (const float*)d_in[11];
    const float* beta  = (const float*)d_in[12];
    float* out = (float*)d_out;

    void *ph, *pnp, *pwn;
    cudaGetSymbolAddress(&ph, g_h);
    cudaGetSymbolAddress(&pnp, g_NP);
    cudaGetSymbolAddress(&pwn, g_Wnode);
    float* hbuf  = (float*)ph;
    float* npbuf = (float*)pnp;
    float* wnode = (float*)pwn;

    // ---- CSR preprocessing (per launch; graph-capturable) ----
    zero_deg<<<(N_NODES + 255) / 256, 256>>>();
    convert_hist<<<(N_EDGES + 255) / 256, 256>>>(ei);
    scan_kernel<<<1, 512>>>();
    scatter_permute<<<N_EDGES / 256, 256>>>(ea);

    combine_kernel<<<1, 384>>>(Wf, bf, Ws, bs, W2, b2);

    // h0 = x @ W1 + b1
    gemm16<92, 32, 1><<<N_NODES / 16, 32>>>(x, W1, 64, b1, hbuf, 64);

    for (int l = 0; l < 3; l++) {
        gemm16<64, 64, 2><<<N_NODES / 16, 64>>>(hbuf, wnode + l * 16384, 256,
                                                (const float*)nullptr, npbuf, 256);
        zero_agg_stats<<<128, 256>>>();
        edge_kernel<<<N_EDGES / 32, 128>>>(l);
        resid_stats<<<256, 256>>>();
        const int last = (l == 2);
        bn_kernel<<<(N_NODES * 64) / 256, 256>>>(gamma, beta, l,
                                                 last ? out : hbuf, last ? 0 : 1);
    }
}

// round 5
// speedup vs baseline: 1.1269x; 1.0370x over previous
#include <cuda_runtime.h>
#include <cstdint>

#define N_NODES 50000
#define N_EDGES 800000

typedef unsigned long long ull;

// ---------------- scratch (device globals; no allocation allowed) ----------
__device__ float g_h[N_NODES * 64];        // node features
__device__ float g_NP[N_NODES * 256];      // per-node projections f_t|f_s|s_t|s_s
__device__ float g_agg[N_NODES * 64];      // message accumulator
__device__ float g_Wcomb[41 * 384];        // edge_attr -> all-layer gate/core pre-act
__device__ ull   g_WcombT[3 * 2 * 32 * 42];// transposed: [layer][mat][lane][k] col-pairs
__device__ float g_bcomb[384];
__device__ float g_Wnode[3 * 64 * 256];    // per-layer node projection weights
__device__ float g_stats[3 * 128];         // per-layer BN column sums / sumsq
// CSR machinery
__device__ int   g_src32[N_EDGES];
__device__ int   g_tgt32[N_EDGES];
__device__ int   g_deg[N_NODES];
__device__ int   g_cursor[N_NODES];
__device__ int   g_srcperm[N_EDGES];
__device__ int   g_tgtperm[N_EDGES];
__device__ float g_eaperm[(size_t)N_EDGES * 48];  // stride 48 (192B, sector-aligned)

// ---------------- f32x2 helpers --------------------------------------------
__device__ __forceinline__ ull fma2(ull a, ull b, ull c) {
    ull d;
    asm("fma.rn.f32x2 %0, %1, %2, %3;" : "=l"(d) : "l"(a), "l"(b), "l"(c));
    return d;
}
__device__ __forceinline__ ull dup2(float v) {
    ull d; unsigned u = __float_as_uint(v);
    asm("mov.b64 %0, {%1, %2};" : "=l"(d) : "r"(u), "r"(u));
    return d;
}
__device__ __forceinline__ float2 unpack2(ull v) {
    unsigned lo, hi;
    asm("mov.b64 {%0, %1}, %2;" : "=r"(lo), "=r"(hi) : "l"(v));
    return make_float2(__uint_as_float(lo), __uint_as_float(hi));
}
__device__ __forceinline__ void red2(float* p, float a, float b) {
    asm volatile("red.global.add.v2.f32 [%0], {%1, %2};" :: "l"(p), "f"(a), "f"(b) : "memory");
}
__device__ __forceinline__ float sigmoidf_(float x) {
    return __fdividef(1.f, 1.f + __expf(-x));
}
__device__ __forceinline__ float softplusf_(float x) {
    return fmaxf(x, 0.f) + __logf(1.f + __expf(-fabsf(x)));
}

// ---------------- preprocessing --------------------------------------------
__global__ void zero_deg() {
    const int i = blockIdx.x * blockDim.x + threadIdx.x;
    if (i < N_NODES) g_deg[i] = 0;
}

__global__ void __launch_bounds__(256) convert_hist(const void* __restrict__ raw) {
    __shared__ int s_is64;
    if (threadIdx.x == 0) {
        const int* r32 = (const int*)raw;
        int is64 = 1;
        for (int i = 0; i < 64; i++)
            if (r32[2 * i + 1] != 0) { is64 = 0; break; }
        s_is64 = is64;
    }
    __syncthreads();
    const int e = blockIdx.x * 256 + threadIdx.x;
    if (e >= N_EDGES) return;
    int s, t;
    if (s_is64) {
        s = (int)((const long long*)raw)[e];
        t = (int)((const long long*)raw)[N_EDGES + e];
    } else {
        s = ((const int*)raw)[e];
        t = ((const int*)raw)[N_EDGES + e];
    }
    s = min(max(s, 0), N_NODES - 1);
    t = min(max(t, 0), N_NODES - 1);
    g_src32[e] = s;
    g_tgt32[e] = t;
    atomicAdd(&g_deg[t], 1);
}

__global__ void __launch_bounds__(512) scan_kernel() {
    __shared__ int ssum[512];
    const int t = threadIdx.x;
    const int base = t * 98;
    const int lim = min(base + 98, N_NODES);
    int s = 0;
    for (int i = base; i < lim; i++) s += g_deg[i];
    ssum[t] = s;
    __syncthreads();
    for (int off = 1; off < 512; off <<= 1) {
        int v = (t >= off) ? ssum[t - off] : 0;
        __syncthreads();
        ssum[t] += v;
        __syncthreads();
    }
    int run = ssum[t] - s;
    for (int i = base; i < lim; i++) {
        g_cursor[i] = run;
        run += g_deg[i];
    }
}

// scatter into target-sorted order, stride-48 rows (cols 41..47 zeroed)
__global__ void __launch_bounds__(256) scatter_permute(const float* __restrict__ ea) {
    const int w = threadIdx.x >> 5, lane = threadIdx.x & 31;
    const int eb = blockIdx.x * 256 + w * 32;
    const int e = eb + lane;
    const int tg = g_tgt32[e];
    const int pos = atomicAdd(&g_cursor[tg], 1);
    g_srcperm[pos] = g_src32[e];
    g_tgtperm[pos] = tg;
#pragma unroll 4
    for (int j = 0; j < 32; j++) {
        int pe = __shfl_sync(0xffffffffu, pos, j);
        const float* s = ea + (size_t)(eb + j) * 41;
        float* d = g_eaperm + (size_t)pe * 48;
        d[lane] = s[lane];                                     // cols 0..31
        if (lane < 16) {
            int c = 32 + lane;                                 // cols 32..47
            d[c] = (c < 41) ? s[c] : 0.f;
        }
    }
}

// ---------------- weight pre-combination (one block) ------------------------
__global__ void __launch_bounds__(384) combine_kernel(
    const float* __restrict__ Wf, const float* __restrict__ bf,
    const float* __restrict__ Ws, const float* __restrict__ bs,
    const float* __restrict__ W2, const float* __restrict__ b2) {
    const int c = threadIdx.x;                 // 0..383
    const int i = c >> 7;                      // layer
    const int r = c & 127;
    const bool isF = r < 64;
    const int j = r & 63;
    const float* WB = isF ? Wf : Ws;
    const float* bB = isF ? bf : bs;

    float wc[64];
#pragma unroll
    for (int k = 0; k < 64; k++) wc[k] = WB[i * 12288 + (128 + k) * 64 + j];

    float bacc = bB[i * 64 + j];
#pragma unroll
    for (int k = 0; k < 64; k++) bacc += b2[k] * wc[k];
    g_bcomb[c] = bacc;

    for (int a = 0; a < 41; a++) {
        float acc = 0.f;
#pragma unroll
        for (int k = 0; k < 64; k++) acc += W2[a * 64 + k] * wc[k];
        g_Wcomb[a * 384 + c] = acc;
    }

    for (int idx = c; idx < 3 * 64 * 256; idx += 384) {
        int l = idx >> 14;
        int rem = idx & 16383;
        int k = rem >> 8;
        int cc = rem & 255;
        int part = cc >> 6;                    // 0:f_t 1:f_s 2:s_t 3:s_s
        int jj = cc & 63;
        const float* S = (part < 2) ? Wf : Ws;
        int row = k + ((part & 1) ? 64 : 0);
        g_Wnode[idx] = S[l * 12288 + row * 64 + jj];
    }

    __syncthreads();

    for (int idx = c; idx < 3 * 2 * 32 * 42; idx += 384) {
        int k = idx % 42;
        int rest = idx / 42;
        int lanep = rest & 31;
        rest >>= 5;
        int mat = rest & 1;
        int lay = rest >> 1;
        ull v = 0ull;
        if (k < 41) {
            unsigned lo = __float_as_uint(g_Wcomb[k * 384 + lay * 128 + mat * 64 + 2 * lanep]);
            unsigned hi = __float_as_uint(g_Wcomb[k * 384 + lay * 128 + mat * 64 + 2 * lanep + 1]);
            v = ((ull)hi << 32) | lo;
        }
        g_WcombT[idx] = v;
    }
}

// ---------------- ROWS-row f32x2 GEMM: out = A[M,K] @ W[K,2*CP*NT] (+bias) --
template <int K, int NT, int CP, int ROWS>
__global__ void __launch_bounds__(NT) gemmRB(const float* __restrict__ A,
                                             const float* __restrict__ W, int ldw,
                                             const float* __restrict__ bias,
                                             float* __restrict__ out, int ldo) {
    __shared__ __align__(16) ull a_s[ROWS][(K + 1) & ~1];
    const int tid = threadIdx.x;
    const int row0 = blockIdx.x * ROWS;

    for (int idx = tid; idx < ROWS * K; idx += NT) {
        int r = idx / K, k = idx - r * K;
        a_s[r][k] = dup2(A[(size_t)row0 * K + idx]);
    }
    if (K & 1) {
        for (int r = tid; r < ROWS; r += NT) a_s[r][K] = 0ull;
    }
    __syncthreads();

    const int c = tid * 2 * CP;
    ull acc[ROWS][CP];
#pragma unroll
    for (int r = 0; r < ROWS; r++)
#pragma unroll
        for (int p = 0; p < CP; p++) acc[r][p] = 0ull;

    const float* Wc = W + c;
#pragma unroll 2
    for (int kk = 0; kk < (K + 1) / 2; kk++) {
        const int k0 = 2 * kk;
        ull w0[CP], w1[CP];
        if (CP == 2) {
            ulonglong2 wv = *(const ulonglong2*)(Wc + (size_t)k0 * ldw);
            w0[0] = wv.x; w0[CP - 1] = wv.y;
        } else {
            w0[0] = *(const ull*)(Wc + (size_t)k0 * ldw);
        }
        if (k0 + 1 < K) {
            if (CP == 2) {
                ulonglong2 wv = *(const ulonglong2*)(Wc + (size_t)(k0 + 1) * ldw);
                w1[0] = wv.x; w1[CP - 1] = wv.y;
            } else {
                w1[0] = *(const ull*)(Wc + (size_t)(k0 + 1) * ldw);
            }
        } else {
#pragma unroll
            for (int p = 0; p < CP; p++) w1[p] = 0ull;
        }
#pragma unroll
        for (int r = 0; r < ROWS; r++) {
            ulonglong2 av = *(const ulonglong2*)&a_s[r][k0];
#pragma unroll
            for (int p = 0; p < CP; p++) {
                acc[r][p] = fma2(w0[p], av.x, acc[r][p]);
                acc[r][p] = fma2(w1[p], av.y, acc[r][p]);
            }
        }
    }

    float2 b[CP];
#pragma unroll
    for (int p = 0; p < CP; p++) {
        b[p] = make_float2(0.f, 0.f);
        if (bias) b[p] = *(const float2*)(bias + c + 2 * p);
    }
#pragma unroll
    for (int r = 0; r < ROWS; r++) {
#pragma unroll
        for (int p = 0; p < CP; p++) {
            float2 v = unpack2(acc[r][p]);
            v.x += b[p].x; v.y += b[p].y;
            *(float2*)&out[(size_t)(row0 + r) * ldo + c + 2 * p] = v;
        }
    }
}

// ---------------- edge kernel: sorted edges, 8/warp, prefetched gathers -----
__global__ void __launch_bounds__(128) edge_kernel(int layer) {
    __shared__ __align__(16) ull ea_s[4][8][48];
    __shared__ int src_s[4][8], tgt_s[4][8];
    const int w = threadIdx.x >> 5, lane = threadIdx.x & 31;
    const int e0 = (blockIdx.x * 4 + w) * 8;
    const int cg = 2 * lane;

    if (lane < 8)       src_s[w][lane] = g_srcperm[e0 + lane];
    else if (lane < 16) tgt_s[w][lane - 8] = g_tgtperm[e0 + lane - 8];

    // stage 8 rows x 48 floats = 96 float4 (aligned, 192B rows)
#pragma unroll
    for (int j = 0; j < 3; j++) {
        int idx = lane + j * 32;
        int r = idx / 12, c4 = idx - r * 12;
        float4 v = *(const float4*)(g_eaperm + (size_t)(e0 + r) * 48 + 4 * c4);
        ulonglong2 p0, p1;
        p0.x = dup2(v.x); p0.y = dup2(v.y);
        p1.x = dup2(v.z); p1.y = dup2(v.w);
        *(ulonglong2*)&ea_s[w][r][4 * c4]     = p0;
        *(ulonglong2*)&ea_s[w][r][4 * c4 + 2] = p1;
    }
    __syncwarp();

    const ull* WG = g_WcombT + ((size_t)(layer * 2 + 0) * 32 + lane) * 42;
    const ull* WC = g_WcombT + ((size_t)(layer * 2 + 1) * 32 + lane) * 42;

    ull accG[8], accC[8];
#pragma unroll
    for (int r = 0; r < 8; r++) { accG[r] = 0ull; accC[r] = 0ull; }

#pragma unroll
    for (int kk = 0; kk < 21; kk++) {
        ulonglong2 wg = *(const ulonglong2*)(WG + 2 * kk);
        ulonglong2 wc = *(const ulonglong2*)(WC + 2 * kk);
#pragma unroll
        for (int r = 0; r < 8; r++) {
            ulonglong2 av = *(const ulonglong2*)&ea_s[w][r][2 * kk];
            accG[r] = fma2(wg.x, av.x, accG[r]);
            accG[r] = fma2(wg.y, av.y, accG[r]);
            accC[r] = fma2(wc.x, av.x, accC[r]);
            accC[r] = fma2(wc.y, av.y, accC[r]);
        }
    }

    // prefetch all 8 source gathers (16 independent LDG.64 in flight)
    float2 fs[8], ss[8];
#pragma unroll
    for (int r = 0; r < 8; r++) {
        const float* NPs = g_NP + (size_t)src_s[w][r] * 256;
        fs[r] = *(const float2*)(NPs + 64 + cg);
        ss[r] = *(const float2*)(NPs + 192 + cg);
    }

    const float2 bg = *(const float2*)(g_bcomb + layer * 128 + cg);
    const float2 bc = *(const float2*)(g_bcomb + layer * 128 + 64 + cg);

    int cur = tgt_s[w][0];
    const float* NPc = g_NP + (size_t)cur * 256;
    float2 ft = *(const float2*)(NPc + cg);
    float2 st = *(const float2*)(NPc + 128 + cg);
    float2 agg = make_float2(0.f, 0.f);

#pragma unroll
    for (int r = 0; r < 8; r++) {
        const int tn = tgt_s[w][r];
        if (tn != cur) {  // warp-uniform branch
            red2(g_agg + (size_t)cur * 64 + cg, agg.x, agg.y);
            cur = tn;
            NPc = g_NP + (size_t)cur * 256;
            ft = *(const float2*)(NPc + cg);
            st = *(const float2*)(NPc + 128 + cg);
            agg.x = 0.f; agg.y = 0.f;
        }
        float2 g = unpack2(accG[r]);
        float2 cp = unpack2(accC[r]);
        g.x += bg.x + ft.x + fs[r].x;    g.y += bg.y + ft.y + fs[r].y;
        cp.x += bc.x + st.x + ss[r].x;   cp.y += bc.y + st.y + ss[r].y;
        agg.x += sigmoidf_(g.x) * softplusf_(cp.x);
        agg.y += sigmoidf_(g.y) * softplusf_(cp.y);
    }
    red2(g_agg + (size_t)cur * 64 + cg, agg.x, agg.y);
}

// ---------------- zero agg + all-layer stats (once, before layer 0) --------
__global__ void zero_agg_stats() {
    const float4 z = make_float4(0.f, 0.f, 0.f, 0.f);
    const int n4 = N_NODES * 16;
    const int gtid = blockIdx.x * blockDim.x + threadIdx.x;
    for (int i = gtid; i < n4; i += gridDim.x * blockDim.x)
        ((float4*)g_agg)[i] = z;
    if (gtid < 3 * 128) g_stats[gtid] = 0.f;
}

// ---------------- residual + BN statistics ---------------------------------
__global__ void __launch_bounds__(256) resid_stats(int layer) {
    const int col = threadIdx.x & 63;
    const int rgrp = threadIdx.x >> 6;  // 0..3
    float s = 0.f, q = 0.f;
    for (int row = blockIdx.x * 4 + rgrp; row < N_NODES; row += gridDim.x * 4) {
        const int idx = row * 64 + col;
        float t = g_h[idx] + g_agg[idx];
        g_h[idx] = t;
        s += t; q += t * t;
    }
    atomicAdd(&g_stats[layer * 128 + col], s);
    atomicAdd(&g_stats[layer * 128 + 64 + col], q);
}

// ---------------- BN normalize (+relu, + zero agg for next layer) -----------
__global__ void __launch_bounds__(256) bn_kernel(const float* __restrict__ gamma,
                                                 const float* __restrict__ beta,
                                                 int layer, float* __restrict__ dst,
                                                 int do_relu, int zero_next) {
    const int i = blockIdx.x * blockDim.x + threadIdx.x;  // exact grid: 3.2M
    const int col = i & 63;
    const float invN = 1.f / (float)N_NODES;
    float mean = g_stats[layer * 128 + col] * invN;
    float var = g_stats[layer * 128 + 64 + col] * invN - mean * mean;
    float inv = rsqrtf(var + 1e-5f);
    float v = (g_h[i] - mean) * inv * gamma[layer * 64 + col] + beta[layer * 64 + col];
    if (do_relu) v = fmaxf(v, 0.f);
    dst[i] = v;
    if (zero_next) g_agg[i] = 0.f;
}

// ---------------- launch ----------------------------------------------------
extern "C" void kernel_launch(void* const* d_in, const int* in_sizes, int n_in,
                              void* d_out, int out_size) {
    const float* x   = (const float*)d_in[0];
    const float* ea  = (const float*)d_in[1];
    const void*  ei  = d_in[2];                 // int32 or int64, detected on device
    const float* W1  = (const float*)d_in[3];
    const float* b1  = (const float*)d_in[4];
    const float* W2  = (const float*)d_in[5];
    const float* b2  = (const float*)d_in[6];
    const float* Wf  = (const float*)d_in[7];
    const float* bf  = (const float*)d_in[8];
    const float* Ws  = (const float*)d_in[9];
    const float* bs  = (const float*)d_in[10];
    const float* gamma = (const float*)d_in[11];
    const float* beta  = (const float*)d_in[12];
    float* out = (float*)d_out;

    void *ph, *pnp, *pwn;
    cudaGetSymbolAddress(&ph, g_h);
    cudaGetSymbolAddress(&pnp, g_NP);
    cudaGetSymbolAddress(&pwn, g_Wnode);
    float* hbuf  = (float*)ph;
    float* npbuf = (float*)pnp;
    float* wnode = (float*)pwn;

    // ---- CSR preprocessing ----
    zero_deg<<<(N_NODES + 255) / 256, 256>>>();
    convert_hist<<<(N_EDGES + 255) / 256, 256>>>(ei);
    scan_kernel<<<1, 512>>>();
    scatter_permute<<<N_EDGES / 256, 256>>>(ea);

    combine_kernel<<<1, 384>>>(Wf, bf, Ws, bs, W2, b2);

    // h0 = x @ W1 + b1   (8 rows/block)
    gemmRB<92, 32, 1, 8><<<N_NODES / 8, 32>>>(x, W1, 64, b1, hbuf, 64);
    zero_agg_stats<<<128, 256>>>();

    for (int l = 0; l < 3; l++) {
        gemmRB<64, 64, 2, 8><<<N_NODES / 8, 64>>>(hbuf, wnode + l * 16384, 256,
                                                  (const float*)nullptr, npbuf, 256);
        edge_kernel<<<N_EDGES / 32, 128>>>(l);
        resid_stats<<<256, 256>>>(l);
        const int last = (l == 2);
        bn_kernel<<<(N_NODES * 64) / 256, 256>>>(gamma, beta, l,
                                                 last ? out : hbuf, last ? 0 : 1,
                                                 last ? 0 : 1);
    }
}